// round 3
// baseline (speedup 1.0000x reference)
#include <cuda_runtime.h>
#include <math.h>

#define LDIM 32
#define HDIM 64
#define PZS  33   // padded stride for per-row logit-partial buffers

typedef unsigned long long ull;

__device__ __forceinline__ ull pack2(float lo, float hi) {
    ull r; asm("mov.b64 %0, {%1, %2};" : "=l"(r) : "f"(lo), "f"(hi)); return r;
}
__device__ __forceinline__ float2 unpack2(ull v) {
    float2 r; asm("mov.b64 {%0, %1}, %2;" : "=f"(r.x), "=f"(r.y) : "l"(v)); return r;
}
#define FMA2(d, a, b, c) \
    asm("fma.rn.f32x2 %0, %1, %2, %3;" : "=l"(d) : "l"(a), "l"(b), "l"(c))

// One warp per sample. Thread t owns output channels {t, t+32}.
// Wc columns live in registers as packed f32x2 pairs (along k).
// u = h + carry-from-above is broadcast via a double-buffered smem buffer.
// Per-step logit partials are staged to smem; the log-softmax reduction is
// done once per row (32 steps, thread t reduces step t) — no SHFLs and no
// exp/log in the hot loop.
__global__ void __launch_bounds__(32) rnn2d_kernel(
    const int*   __restrict__ x,     // (B, 32, 32) int32, values in {0,1}
    const float* __restrict__ Win,   // (2, 64)
    const float* __restrict__ Wc,    // (64, 64)
    const float* __restrict__ bc,    // (64,)
    const float* __restrict__ Wout,  // (64, 2)
    const float* __restrict__ bout,  // (2,)
    float*       __restrict__ out)   // (B,)
{
    const int b = blockIdx.x;
    const int t = threadIdx.x;          // 0..31

    __shared__ float2 Hprev2[LDIM][LDIM];   // [col][t] — thread-private columns
    __shared__ float  ubuf[2][HDIM];        // double-buffered u (k-order)
    __shared__ int    xrow[2][LDIM];        // current / previous x rows
    __shared__ float  pz0buf[LDIM * PZS];   // [step][thread] logit partials
    __shared__ float  pz1buf[LDIM * PZS];

    // ---- pack Wc columns j0=t, j1=t+32 into f32x2 register pairs along k ----
    ull wcp0[HDIM / 2], wcp1[HDIM / 2];
#pragma unroll
    for (int k = 0; k < HDIM / 2; ++k) {
        wcp0[k] = pack2(Wc[(2 * k) * HDIM + t],      Wc[(2 * k + 1) * HDIM + t]);
        wcp1[k] = pack2(Wc[(2 * k) * HDIM + t + 32], Wc[(2 * k + 1) * HDIM + t + 32]);
    }
    const float win00 = Win[t],        win10 = Win[HDIM + t];
    const float win01 = Win[t + 32],   win11 = Win[HDIM + t + 32];
    const float bc0   = bc[t],         bc1   = bc[t + 32];
    const float wo00  = Wout[t * 2],         wo01 = Wout[t * 2 + 1];
    const float wo10  = Wout[(t + 32) * 2],  wo11 = Wout[(t + 32) * 2 + 1];
    const float bo0   = bout[0],       bo1   = bout[1];

#pragma unroll
    for (int c = 0; c < LDIM; ++c) Hprev2[c][t] = make_float2(0.0f, 0.0f);

    const int* xb = x + b * LDIM * LDIM;

    float logp = 0.0f;
    float2 hp = Hprev2[0][t];           // prefetched carry-from-above (zeros)

    for (int i = 0; i < LDIM; ++i) {
        __syncwarp();
        xrow[i & 1][t] = xb[i * LDIM + t];

        const int dir  = (i & 1) ? -1 : 1;
        const int cur  = i & 1;
        const int prev = cur ^ 1;

        float h0 = 0.0f, h1 = 0.0f;     // row-scan carry
        int   xL = 0;                   // x at previous scan position

#pragma unroll 2
        for (int jj = 0; jj < LDIM; ++jj) {
            const int c = (i & 1) ? (LDIM - 1 - jj) : jj;
            const int p = jj & 1;

            // u = h + carry-from-above (hp was prefetched)
            const float u0 = h0 + hp.x;
            const float u1 = h1 + hp.y;
            ubuf[p][t]      = u0;
            ubuf[p][t + 32] = u1;

            __syncwarp();

            const int xC = xrow[cur][c];
            const int xU = (i > 0) ? xrow[prev][c] : 0;

            // base = bc + newR @ Win (off the recurrence chain)
            float r0 = bc0, r1 = bc1;
            if (jj > 0) { r0 += xL ? win10 : win00;  r1 += xL ? win11 : win01; }
            if (i  > 0) { r0 += xU ? win10 : win00;  r1 += xU ? win11 : win01; }

            // 64-wide matvec with packed f32x2 FMAs, accumulators seeded with r
            ull a00 = pack2(r0, 0.0f), a01 = 0;
            ull a10 = pack2(r1, 0.0f), a11 = 0;
            const ulonglong2* up = (const ulonglong2*)ubuf[p];
#pragma unroll
            for (int k = 0; k < HDIM / 4; ++k) {
                const ulonglong2 uv = up[k];       // pairs (4k,4k+1) and (4k+2,4k+3)
                FMA2(a00, uv.x, wcp0[2 * k],     a00);
                FMA2(a10, uv.x, wcp1[2 * k],     a10);
                FMA2(a01, uv.y, wcp0[2 * k + 1], a01);
                FMA2(a11, uv.y, wcp1[2 * k + 1], a11);
            }
            const float2 f00 = unpack2(a00), f01 = unpack2(a01);
            const float2 f10 = unpack2(a10), f11 = unpack2(a11);
            const float s0 = (f00.x + f00.y) + (f01.x + f01.y);
            const float s1 = (f10.x + f10.y) + (f11.x + f11.y);

            // elu (alpha = 1), fast-math exp
            const float nh0 = (s0 > 0.0f) ? s0 : (__expf(s0) - 1.0f);
            const float nh1 = (s1 > 0.0f) ? s1 : (__expf(s1) - 1.0f);

            // stage per-thread logit partials for the per-row reduction
            pz0buf[jj * PZS + t] = nh0 * wo00 + nh1 * wo10;
            pz1buf[jj * PZS + t] = nh0 * wo01 + nh1 * wo11;

            // writeback + prefetch next carry-from-above
            Hprev2[c][t] = make_float2(nh0, nh1);
            const int cn = (jj < LDIM - 1) ? (c + dir) : c;  // next row starts at same col
            hp = Hprev2[cn][t];

            h0 = nh0;
            h1 = nh1;
            xL = xC;
        }

        // ---- per-row logp reduction: thread t handles step jj = t ----
        __syncwarp();
        {
            float s0a = 0.f, s0b = 0.f, s0c = 0.f, s0d = 0.f;
            float s1a = 0.f, s1b = 0.f, s1c = 0.f, s1d = 0.f;
            const float* q0 = &pz0buf[t * PZS];
            const float* q1 = &pz1buf[t * PZS];
#pragma unroll
            for (int k = 0; k < LDIM; k += 4) {
                s0a += q0[k];     s0b += q0[k + 1];
                s0c += q0[k + 2]; s0d += q0[k + 3];
                s1a += q1[k];     s1b += q1[k + 1];
                s1c += q1[k + 2]; s1d += q1[k + 3];
            }
            const float z0 = (s0a + s0b) + (s0c + s0d) + bo0;
            const float z1 = (s1a + s1b) + (s1c + s1d) + bo1;
            const float m   = fmaxf(z0, z1);
            const float lse = m + __logf(__expf(z0 - m) + __expf(z1 - m));
            const int   cc  = (i & 1) ? (LDIM - 1 - t) : t;
            const int   xC  = xrow[i & 1][cc];
            float lp = (xC ? z1 : z0) - lse;
            if (lp != lp) lp = -35.0f;
            logp += lp;
        }
        __syncwarp();   // reduction reads done before next row overwrites pzbuf
    }

    // each thread holds the logp of the steps it reduced — combine once
#pragma unroll
    for (int off = 16; off > 0; off >>= 1)
        logp += __shfl_xor_sync(0xffffffffu, logp, off);

    if (t == 0) out[b] = 0.5f * logp;
}

extern "C" void kernel_launch(void* const* d_in, const int* in_sizes, int n_in,
                              void* d_out, int out_size) {
    const int*   x    = (const int*)  d_in[0];
    const float* Win  = (const float*)d_in[1];
    const float* Wc   = (const float*)d_in[2];
    const float* bc   = (const float*)d_in[3];
    const float* Wout = (const float*)d_in[4];
    const float* bout = (const float*)d_in[5];
    float* out = (float*)d_out;

    const int B = in_sizes[0] / (LDIM * LDIM);
    rnn2d_kernel<<<B, 32>>>(x, Win, Wc, bc, Wout, bout, out);
}